// round 3
// baseline (speedup 1.0000x reference)
#include <cuda_runtime.h>
#include <cuda_bf16.h>

#define USER_NUM 100000
#define ITEM_NUM 50000
#define CONCEPT_NUM 2000
#define EMB 64
#define NTOT (USER_NUM + ITEM_NUM)
#define N_LAYERS 3
#define EPS_V 0.1f
#define NNZ_ADJ 2400000
#define NNZ_PRE 16000
#define NNZ_IC 250000

// -------- device scratch (static; no runtime allocation) --------
__device__ float g_bufA[NTOT * EMB];   // ego / tmp ping-pong
__device__ float g_bufB[NTOT * EMB];
__device__ float g_acc [NTOT * EMB];
__device__ float g_cA  [CONCEPT_NUM * EMB];
__device__ float g_cB  [CONCEPT_NUM * EMB];

// -------- edge-parallel SpMM: y[rows[e]+off] += scale*vals[e]*x[cols[e]] --------
// 16 threads per edge, each handles one float4 (4 floats) of the 64-dim row.
__global__ void spmm_kernel(const int* __restrict__ rows,
                            const int* __restrict__ cols,
                            const float* __restrict__ vals,
                            const float4* __restrict__ x,
                            float4* __restrict__ y,
                            int nnz, float scale, int row_off)
{
    unsigned gid = blockIdx.x * blockDim.x + threadIdx.x;
    unsigned e = gid >> 4;
    if (e >= (unsigned)nnz) return;
    unsigned f = gid & 15u;
    int r = __ldg(rows + e) + row_off;
    int c = __ldg(cols + e);
    float v = __ldg(vals + e) * scale;
    float4 xv = __ldg(x + (unsigned)c * 16u + f);
    float4* dst = y + (unsigned)r * 16u + f;
    asm volatile("red.global.add.v4.f32 [%0], {%1,%2,%3,%4};"
                 :: "l"(dst), "f"(v * xv.x), "f"(v * xv.y), "f"(v * xv.z), "f"(v * xv.w)
                 : "memory");
}

__device__ __forceinline__ float sgnf(float x) {
    return (x > 0.0f) ? 1.0f : ((x < 0.0f) ? -1.0f : 0.0f);
}

// -------- perturb + accumulate: ego += sign(ego)*normalize(noise)*eps; acc += ego --------
// 32 threads per row, each handling 2 elements (float2).
__global__ void perturb_kernel(float* __restrict__ ego,
                               const float* __restrict__ noise,
                               float* __restrict__ acc,
                               float* __restrict__ out,
                               int write_out)
{
    int row = blockIdx.x * (blockDim.x >> 5) + (threadIdx.x >> 5);
    if (row >= NTOT) return;
    int lane = threadIdx.x & 31;

    const float2* nrow = (const float2*)(noise + (size_t)row * EMB);
    float2 nv = __ldg(nrow + lane);
    float ss = nv.x * nv.x + nv.y * nv.y;
    #pragma unroll
    for (int o = 16; o > 0; o >>= 1)
        ss += __shfl_xor_sync(0xFFFFFFFFu, ss, o);
    float nrm = fmaxf(sqrtf(ss), 1e-12f);
    float s = EPS_V / nrm;

    float2* ep = (float2*)(ego + (size_t)row * EMB) + lane;
    float2 e = *ep;
    e.x += sgnf(e.x) * nv.x * s;
    e.y += sgnf(e.y) * nv.y * s;
    *ep = e;

    float2* ap = (float2*)(acc + (size_t)row * EMB) + lane;
    float2 a = *ap;
    a.x += e.x;
    a.y += e.y;
    *ap = a;

    if (write_out) {
        const float inv = 1.0f / (float)N_LAYERS;
        float2* op = (float2*)(out + (size_t)row * EMB) + lane;
        float2 o2;
        o2.x = a.x * inv;
        o2.y = a.y * inv;
        *op = o2;
    }
}

extern "C" void kernel_launch(void* const* d_in, const int* in_sizes, int n_in,
                              void* d_out, int out_size)
{
    const float* user_emb    = (const float*)d_in[0];
    const float* item_emb    = (const float*)d_in[1];
    const float* concept_emb = (const float*)d_in[2];
    const int*   adj_rows    = (const int*)d_in[3];
    const int*   adj_cols    = (const int*)d_in[4];
    const float* adj_vals    = (const float*)d_in[5];
    const int*   pre_rows    = (const int*)d_in[6];
    const int*   pre_cols    = (const int*)d_in[7];
    const float* pre_vals    = (const float*)d_in[8];
    const int*   ic_rows     = (const int*)d_in[9];
    const int*   ic_cols     = (const int*)d_in[10];
    const float* ic_vals     = (const float*)d_in[11];
    const float* noise       = (const float*)d_in[12];
    float* out = (float*)d_out;

    float *bufA, *bufB, *acc, *cA, *cB;
    cudaGetSymbolAddress((void**)&bufA, g_bufA);
    cudaGetSymbolAddress((void**)&bufB, g_bufB);
    cudaGetSymbolAddress((void**)&acc,  g_acc);
    cudaGetSymbolAddress((void**)&cA,   g_cA);
    cudaGetSymbolAddress((void**)&cB,   g_cB);

    const size_t EGO_BYTES = (size_t)NTOT * EMB * sizeof(float);
    const size_t C_BYTES   = (size_t)CONCEPT_NUM * EMB * sizeof(float);

    // init: acc = 0, ego = [user_emb; item_emb], c = concept_emb
    cudaMemsetAsync(acc, 0, EGO_BYTES, 0);
    cudaMemcpyAsync(bufA, user_emb, (size_t)USER_NUM * EMB * sizeof(float),
                    cudaMemcpyDeviceToDevice, 0);
    cudaMemcpyAsync(bufA + (size_t)USER_NUM * EMB, item_emb,
                    (size_t)ITEM_NUM * EMB * sizeof(float),
                    cudaMemcpyDeviceToDevice, 0);
    cudaMemcpyAsync(cA, concept_emb, C_BYTES, cudaMemcpyDeviceToDevice, 0);

    float* ego = bufA;
    float* tmp = bufB;
    float* cin = cA;
    float* cout = cB;

    const unsigned BLK = 256;
    const unsigned adj_grid = (unsigned)(((unsigned long long)NNZ_ADJ * 16ull + BLK - 1) / BLK);
    const unsigned pre_grid = (unsigned)(((unsigned long long)NNZ_PRE * 16ull + BLK - 1) / BLK);
    const unsigned ic_grid  = (unsigned)(((unsigned long long)NNZ_IC  * 16ull + BLK - 1) / BLK);
    const unsigned pert_grid = (NTOT + 7) / 8;  // 8 rows per 256-thread block

    for (int k = 0; k < N_LAYERS; k++) {
        // tmp = spmm(adj, ego)
        cudaMemsetAsync(tmp, 0, EGO_BYTES, 0);
        spmm_kernel<<<adj_grid, BLK>>>(adj_rows, adj_cols, adj_vals,
                                       (const float4*)ego, (float4*)tmp,
                                       NNZ_ADJ, 1.0f, 0);
        // cout = cin + spmm(pre, cin)
        cudaMemcpyAsync(cout, cin, C_BYTES, cudaMemcpyDeviceToDevice, 0);
        spmm_kernel<<<pre_grid, BLK>>>(pre_rows, pre_cols, pre_vals,
                                       (const float4*)cin, (float4*)cout,
                                       NNZ_PRE, 1.0f, 0);
        // tmp[item part] += 0.1 * spmm(ic, cout)
        spmm_kernel<<<ic_grid, BLK>>>(ic_rows, ic_cols, ic_vals,
                                      (const float4*)cout, (float4*)tmp,
                                      NNZ_IC, 0.1f, USER_NUM);
        // perturb + accumulate (writes out on last layer)
        perturb_kernel<<<pert_grid, BLK>>>(tmp, noise + (size_t)k * NTOT * EMB,
                                           acc, out, (k == N_LAYERS - 1) ? 1 : 0);
        // swap ping-pong buffers
        float* t = ego; ego = tmp; tmp = t;
        t = cin; cin = cout; cout = t;
    }
}

// round 4
// speedup vs baseline: 1.5399x; 1.5399x over previous
#include <cuda_runtime.h>
#include <cuda_bf16.h>

#define USER_NUM 100000
#define ITEM_NUM 50000
#define CONCEPT_NUM 2000
#define EMB 64
#define NTOT (USER_NUM + ITEM_NUM)
#define N_LAYERS 3
#define EPS_V 0.1f
#define NNZ_ADJ 2400000
#define NNZ_PRE 16000
#define NNZ_IC 250000

#define SCAN_BLK 1024
#define SCAN_NBLK ((NTOT + SCAN_BLK - 1) / SCAN_BLK)   // 147

// -------- device scratch (static; no runtime allocation) --------
__device__ float g_bufA[NTOT * EMB];   // ego / tmp ping-pong
__device__ float g_bufB[NTOT * EMB];
__device__ float g_acc [NTOT * EMB];
__device__ float g_cA  [CONCEPT_NUM * EMB];
__device__ float g_cB  [CONCEPT_NUM * EMB];
// CSR build scratch
__device__ int   g_cnt     [NTOT];        // histogram, then cursor
__device__ int   g_scantmp [NTOT];        // per-chunk inclusive scan
__device__ int   g_rowptr  [NTOT + 1];
__device__ int   g_bsums   [256];         // SCAN_NBLK used
__device__ int   g_colS    [NNZ_ADJ];
__device__ float g_valS    [NNZ_ADJ];

// ==================== CSR construction ====================

__global__ void hist_kernel(const int* __restrict__ rows, int* __restrict__ cnt)
{
    int e = blockIdx.x * blockDim.x + threadIdx.x;
    if (e < NNZ_ADJ) atomicAdd(&cnt[__ldg(rows + e)], 1);
}

// per-1024-chunk inclusive scan; chunk totals to bsums
__global__ void scan_block_kernel(const int* __restrict__ cnt,
                                  int* __restrict__ scantmp,
                                  int* __restrict__ bsums)
{
    __shared__ int sh[SCAN_BLK];
    int i = blockIdx.x * SCAN_BLK + threadIdx.x;
    int v = (i < NTOT) ? cnt[i] : 0;
    sh[threadIdx.x] = v;
    __syncthreads();
    for (int o = 1; o < SCAN_BLK; o <<= 1) {
        int t = (threadIdx.x >= o) ? sh[threadIdx.x - o] : 0;
        __syncthreads();
        sh[threadIdx.x] += t;
        __syncthreads();
    }
    if (i < NTOT) scantmp[i] = sh[threadIdx.x];
    if (threadIdx.x == SCAN_BLK - 1) bsums[blockIdx.x] = sh[SCAN_BLK - 1];
}

// single block: exclusive scan of the chunk sums (SCAN_NBLK <= 256)
__global__ void scan_sums_kernel(int* __restrict__ bsums)
{
    __shared__ int sh[256];
    int tid = threadIdx.x;
    int v = (tid < SCAN_NBLK) ? bsums[tid] : 0;
    sh[tid] = v;
    __syncthreads();
    for (int o = 1; o < 256; o <<= 1) {
        int t = (tid >= o) ? sh[tid - o] : 0;
        __syncthreads();
        sh[tid] += t;
        __syncthreads();
    }
    if (tid < SCAN_NBLK) bsums[tid] = sh[tid] - v;   // exclusive
}

__global__ void finalize_rowptr_kernel(const int* __restrict__ scantmp,
                                       const int* __restrict__ bsums,
                                       int* __restrict__ rowptr)
{
    int i = blockIdx.x * blockDim.x + threadIdx.x;
    if (i >= NTOT) return;
    rowptr[i + 1] = scantmp[i] + bsums[i >> 10];
    if (i == 0) rowptr[0] = 0;
}

__global__ void scatter_kernel(const int* __restrict__ rows,
                               const int* __restrict__ cols,
                               const float* __restrict__ vals,
                               int* __restrict__ cursor,
                               int* __restrict__ colS,
                               float* __restrict__ valS)
{
    int e = blockIdx.x * blockDim.x + threadIdx.x;
    if (e >= NNZ_ADJ) return;
    int r = __ldg(rows + e);
    int p = atomicAdd(&cursor[r], 1);
    colS[p] = __ldg(cols + e);
    valS[p] = __ldg(vals + e);
}

// ==================== CSR SpMM: one warp per row, float2 lanes ====================

__global__ void spmm_csr_kernel(const int* __restrict__ rowptr,
                                const int* __restrict__ colS,
                                const float* __restrict__ valS,
                                const float2* __restrict__ x,
                                float2* __restrict__ y)
{
    int row = blockIdx.x * (blockDim.x >> 5) + (threadIdx.x >> 5);
    if (row >= NTOT) return;
    int lane = threadIdx.x & 31;

    int p   = __ldg(rowptr + row);
    int end = __ldg(rowptr + row + 1);

    float2 acc = make_float2(0.0f, 0.0f);

    for (; p + 3 < end; p += 4) {
        int c0 = __ldg(colS + p);
        int c1 = __ldg(colS + p + 1);
        int c2 = __ldg(colS + p + 2);
        int c3 = __ldg(colS + p + 3);
        float v0 = __ldg(valS + p);
        float v1 = __ldg(valS + p + 1);
        float v2 = __ldg(valS + p + 2);
        float v3 = __ldg(valS + p + 3);
        float2 x0 = __ldg(x + (size_t)c0 * 32 + lane);
        float2 x1 = __ldg(x + (size_t)c1 * 32 + lane);
        float2 x2 = __ldg(x + (size_t)c2 * 32 + lane);
        float2 x3 = __ldg(x + (size_t)c3 * 32 + lane);
        acc.x += v0 * x0.x + v1 * x1.x + v2 * x2.x + v3 * x3.x;
        acc.y += v0 * x0.y + v1 * x1.y + v2 * x2.y + v3 * x3.y;
    }
    for (; p < end; p++) {
        int c = __ldg(colS + p);
        float v = __ldg(valS + p);
        float2 xv = __ldg(x + (size_t)c * 32 + lane);
        acc.x += v * xv.x;
        acc.y += v * xv.y;
    }
    y[(size_t)row * 32 + lane] = acc;
}

// ==================== small atomic edge-parallel SpMM (pre / ic) ====================

__global__ void spmm_atomic_kernel(const int* __restrict__ rows,
                                   const int* __restrict__ cols,
                                   const float* __restrict__ vals,
                                   const float4* __restrict__ x,
                                   float4* __restrict__ y,
                                   int nnz, float scale, int row_off)
{
    unsigned gid = blockIdx.x * blockDim.x + threadIdx.x;
    unsigned e = gid >> 4;
    if (e >= (unsigned)nnz) return;
    unsigned f = gid & 15u;
    int r = __ldg(rows + e) + row_off;
    int c = __ldg(cols + e);
    float v = __ldg(vals + e) * scale;
    float4 xv = __ldg(x + (unsigned)c * 16u + f);
    float4* dst = y + (unsigned)r * 16u + f;
    asm volatile("red.global.add.v4.f32 [%0], {%1,%2,%3,%4};"
                 :: "l"(dst), "f"(v * xv.x), "f"(v * xv.y), "f"(v * xv.z), "f"(v * xv.w)
                 : "memory");
}

// ==================== perturb + accumulate ====================

__device__ __forceinline__ float sgnf(float x) {
    return (x > 0.0f) ? 1.0f : ((x < 0.0f) ? -1.0f : 0.0f);
}

__global__ void perturb_kernel(float* __restrict__ ego,
                               const float* __restrict__ noise,
                               float* __restrict__ acc,
                               float* __restrict__ out,
                               int first, int last)
{
    int row = blockIdx.x * (blockDim.x >> 5) + (threadIdx.x >> 5);
    if (row >= NTOT) return;
    int lane = threadIdx.x & 31;

    const float2* nrow = (const float2*)(noise + (size_t)row * EMB);
    float2 nv = __ldg(nrow + lane);
    float ss = nv.x * nv.x + nv.y * nv.y;
    #pragma unroll
    for (int o = 16; o > 0; o >>= 1)
        ss += __shfl_xor_sync(0xFFFFFFFFu, ss, o);
    float nrm = fmaxf(sqrtf(ss), 1e-12f);
    float s = EPS_V / nrm;

    float2* ep = (float2*)(ego + (size_t)row * EMB) + lane;
    float2 e = *ep;
    e.x += sgnf(e.x) * nv.x * s;
    e.y += sgnf(e.y) * nv.y * s;
    *ep = e;

    float2* ap = (float2*)(acc + (size_t)row * EMB) + lane;
    float2 a;
    if (first) {
        a = e;
    } else {
        a = *ap;
        a.x += e.x;
        a.y += e.y;
    }
    if (!last) {
        *ap = a;
    } else {
        const float inv = 1.0f / (float)N_LAYERS;
        float2* op = (float2*)(out + (size_t)row * EMB) + lane;
        float2 o2;
        o2.x = a.x * inv;
        o2.y = a.y * inv;
        *op = o2;
    }
}

// ==================== host ====================

extern "C" void kernel_launch(void* const* d_in, const int* in_sizes, int n_in,
                              void* d_out, int out_size)
{
    const float* user_emb    = (const float*)d_in[0];
    const float* item_emb    = (const float*)d_in[1];
    const float* concept_emb = (const float*)d_in[2];
    const int*   adj_rows    = (const int*)d_in[3];
    const int*   adj_cols    = (const int*)d_in[4];
    const float* adj_vals    = (const float*)d_in[5];
    const int*   pre_rows    = (const int*)d_in[6];
    const int*   pre_cols    = (const int*)d_in[7];
    const float* pre_vals    = (const float*)d_in[8];
    const int*   ic_rows     = (const int*)d_in[9];
    const int*   ic_cols     = (const int*)d_in[10];
    const float* ic_vals     = (const float*)d_in[11];
    const float* noise       = (const float*)d_in[12];
    float* out = (float*)d_out;

    float *bufA, *bufB, *acc, *cA, *cB, *valS;
    int *cnt, *scantmp, *rowptr, *bsums, *colS;
    cudaGetSymbolAddress((void**)&bufA,    g_bufA);
    cudaGetSymbolAddress((void**)&bufB,    g_bufB);
    cudaGetSymbolAddress((void**)&acc,     g_acc);
    cudaGetSymbolAddress((void**)&cA,      g_cA);
    cudaGetSymbolAddress((void**)&cB,      g_cB);
    cudaGetSymbolAddress((void**)&cnt,     g_cnt);
    cudaGetSymbolAddress((void**)&scantmp, g_scantmp);
    cudaGetSymbolAddress((void**)&rowptr,  g_rowptr);
    cudaGetSymbolAddress((void**)&bsums,   g_bsums);
    cudaGetSymbolAddress((void**)&colS,    g_colS);
    cudaGetSymbolAddress((void**)&valS,    g_valS);

    const size_t C_BYTES = (size_t)CONCEPT_NUM * EMB * sizeof(float);

    // ---- init ego + concept ----
    cudaMemcpyAsync(bufA, user_emb, (size_t)USER_NUM * EMB * sizeof(float),
                    cudaMemcpyDeviceToDevice, 0);
    cudaMemcpyAsync(bufA + (size_t)USER_NUM * EMB, item_emb,
                    (size_t)ITEM_NUM * EMB * sizeof(float),
                    cudaMemcpyDeviceToDevice, 0);
    cudaMemcpyAsync(cA, concept_emb, C_BYTES, cudaMemcpyDeviceToDevice, 0);

    // ---- build CSR of adj (reused by all 3 layers) ----
    cudaMemsetAsync(cnt, 0, NTOT * sizeof(int), 0);
    hist_kernel<<<(NNZ_ADJ + 255) / 256, 256>>>(adj_rows, cnt);
    scan_block_kernel<<<SCAN_NBLK, SCAN_BLK>>>(cnt, scantmp, bsums);
    scan_sums_kernel<<<1, 256>>>(bsums);
    finalize_rowptr_kernel<<<(NTOT + 255) / 256, 256>>>(scantmp, bsums, rowptr);
    cudaMemcpyAsync(cnt, rowptr, NTOT * sizeof(int), cudaMemcpyDeviceToDevice, 0);
    scatter_kernel<<<(NNZ_ADJ + 255) / 256, 256>>>(adj_rows, adj_cols, adj_vals,
                                                   cnt, colS, valS);

    float* ego = bufA;
    float* tmp = bufB;
    float* cin = cA;
    float* cout = cB;

    const unsigned BLK = 256;
    const unsigned csr_grid  = (NTOT + 7) / 8;   // 8 warps (rows) per block
    const unsigned pre_grid  = (unsigned)(((unsigned long long)NNZ_PRE * 16ull + BLK - 1) / BLK);
    const unsigned ic_grid   = (unsigned)(((unsigned long long)NNZ_IC  * 16ull + BLK - 1) / BLK);
    const unsigned pert_grid = (NTOT + 7) / 8;

    for (int k = 0; k < N_LAYERS; k++) {
        // tmp = spmm(adj, ego)   (write-once: no memset needed)
        spmm_csr_kernel<<<csr_grid, BLK>>>(rowptr, colS, valS,
                                           (const float2*)ego, (float2*)tmp);
        // cout = cin + spmm(pre, cin)
        cudaMemcpyAsync(cout, cin, C_BYTES, cudaMemcpyDeviceToDevice, 0);
        spmm_atomic_kernel<<<pre_grid, BLK>>>(pre_rows, pre_cols, pre_vals,
                                              (const float4*)cin, (float4*)cout,
                                              NNZ_PRE, 1.0f, 0);
        // tmp[item part] += 0.1 * spmm(ic, cout)
        spmm_atomic_kernel<<<ic_grid, BLK>>>(ic_rows, ic_cols, ic_vals,
                                             (const float4*)cout, (float4*)tmp,
                                             NNZ_IC, 0.1f, USER_NUM);
        // perturb + accumulate (+ write out on last layer)
        perturb_kernel<<<pert_grid, BLK>>>(tmp, noise + (size_t)k * NTOT * EMB,
                                           acc, out,
                                           (k == 0) ? 1 : 0,
                                           (k == N_LAYERS - 1) ? 1 : 0);
        float* t = ego; ego = tmp; tmp = t;
        t = cin; cin = cout; cout = t;
    }
}